// round 16
// baseline (speedup 1.0000x reference)
#include <cuda_runtime.h>

typedef unsigned long long u64;

#define NNODES 25000
#define CMSG   200
#define EMAX   400000

// ---------------- scratch (no allocation allowed -> device globals) ----------
static __device__ float g_xr[NNODES * 20];
static __device__ float g_pi[NNODES * CMSG];
static __device__ float g_pj[NNODES * CMSG];
static __device__ float g_bufA[NNODES * 20];
static __device__ float g_bufB[NNODES * 20];
static __device__ int   g_src[EMAX];
static __device__ int   g_dst[EMAX];

// ---------------- packed fp32x2 helpers --------------------------------------
__device__ __forceinline__ u64 pack2(float lo, float hi) {
    u64 r; asm("mov.b64 %0, {%1, %2};" : "=l"(r) : "f"(lo), "f"(hi)); return r;
}
__device__ __forceinline__ u64 packbb(float v) { return pack2(v, v); }
__device__ __forceinline__ void fma2(u64& d, u64 a, u64 b) {
    asm("fma.rn.f32x2 %0, %1, %2, %0;" : "+l"(d) : "l"(a), "l"(b));
}
__device__ __forceinline__ float2 un2(u64 v) {
    float2 f; asm("mov.b64 {%0, %1}, %2;" : "=f"(f.x), "=f"(f.y) : "l"(v)); return f;
}

// ---------------- edge conversion with inline per-block detect ----------------
__global__ void convert_kernel(const void* __restrict__ edges_raw, int E) {
    __shared__ int s_is64;
    int tid = threadIdx.x;
    if (tid < 32) {
        int idx = 2 * tid + 1;                  // high words of first 32 int64
        int v = (idx < 2 * E) ? ((const int*)edges_raw)[idx] : 0;
        unsigned nz = __ballot_sync(0xFFFFFFFFu, v != 0);
        if (tid == 0) s_is64 = (nz == 0) ? 1 : 0;
    }
    __syncthreads();
    int e = blockIdx.x * blockDim.x + tid;
    if (e >= E) return;
    if (s_is64) {
        const long long* p = (const long long*)edges_raw;
        g_src[e] = (int)p[e];
        g_dst[e] = (int)p[E + e];
    } else {
        const int* p = (const int*)edges_raw;
        g_src[e] = p[e];
        g_dst[e] = p[E + e];
    }
}

// ---------------- d-layer node kernel ----------------------------------------
__global__ void node_d_kernel(const float* __restrict__ feat,
                              const float* __restrict__ W1, const float* __restrict__ b1,
                              float* __restrict__ xr, float* __restrict__ out) {
    int n = blockIdx.x * blockDim.x + threadIdx.x;
    if (n >= NNODES) return;
    float x = __ldg(feat + n);
    xr[n] = x;
    float4* o4 = reinterpret_cast<float4*>(out + n * 20);
    const float4* w4 = reinterpret_cast<const float4*>(W1);
    const float4* b4 = reinterpret_cast<const float4*>(b1);
#pragma unroll
    for (int g = 0; g < 5; g++) {
        float4 w = __ldg(w4 + g);
        float4 b = __ldg(b4 + g);
        o4[g] = make_float4(fmaf(x, w.x, b.x), fmaf(x, w.y, b.y),
                            fmaf(x, w.z, b.z), fmaf(x, w.w, b.w));
    }
}

// ---------------- generic node precompute (C_IN = 20) ------------------------
template <int C_OUT>
__global__ void node_kernel(const float* __restrict__ xin,
                            const float* __restrict__ W1, const float* __restrict__ b1,
                            const float* __restrict__ Wm1, const float* __restrict__ bm1,
                            float* __restrict__ xr,
                            float4* __restrict__ pi4, float4* __restrict__ pj4,
                            float* __restrict__ outbuf) {
    constexpr int C_IN = 20;
    constexpr int K4   = CMSG / 4;            // 50
    constexpr int GL   = (C_OUT + 3) / 4;
    constexpr int TOTG = K4 + GL;             // 55 or 51
    int idx = blockIdx.x * blockDim.x + threadIdx.x;
    if (idx >= NNODES * TOTG) return;
    int n = idx / TOTG;
    int g = idx - n * TOTG;

    float xv[C_IN];
    {
        const float4* x4 = reinterpret_cast<const float4*>(xin + (long)n * C_IN);
#pragma unroll
        for (int q = 0; q < C_IN / 4; q++) {
            float4 v = __ldg(x4 + q);
            xv[4 * q + 0] = fmaxf(v.x, 0.f);
            xv[4 * q + 1] = fmaxf(v.y, 0.f);
            xv[4 * q + 2] = fmaxf(v.z, 0.f);
            xv[4 * q + 3] = fmaxf(v.w, 0.f);
        }
    }
    if (g == 0) {
        float4* xr4 = reinterpret_cast<float4*>(xr + (long)n * C_IN);
#pragma unroll
        for (int q = 0; q < C_IN / 4; q++)
            xr4[q] = make_float4(xv[4 * q], xv[4 * q + 1], xv[4 * q + 2], xv[4 * q + 3]);
    }

    if (g < K4) {
        const float4* W4 = reinterpret_cast<const float4*>(Wm1);  // [2*C_IN][K4]
        float4 ai = __ldg(reinterpret_cast<const float4*>(bm1) + g);
        float4 aj = make_float4(0.f, 0.f, 0.f, 0.f);
#pragma unroll
        for (int c = 0; c < C_IN; c++) {
            float4 wi = __ldg(W4 + c * K4 + g);
            ai.x = fmaf(xv[c], wi.x, ai.x);
            ai.y = fmaf(xv[c], wi.y, ai.y);
            ai.z = fmaf(xv[c], wi.z, ai.z);
            ai.w = fmaf(xv[c], wi.w, ai.w);
            float4 wj = __ldg(W4 + (C_IN + c) * K4 + g);
            aj.x = fmaf(xv[c], wj.x, aj.x);
            aj.y = fmaf(xv[c], wj.y, aj.y);
            aj.z = fmaf(xv[c], wj.z, aj.z);
            aj.w = fmaf(xv[c], wj.w, aj.w);
        }
        pi4[(long)n * K4 + g] = ai;
        pj4[(long)n * K4 + g] = aj;
    } else {
        int gl = g - K4;
        if constexpr (C_OUT % 4 == 0) {
            float4 acc = __ldg(reinterpret_cast<const float4*>(b1) + gl);
#pragma unroll
            for (int c = 0; c < C_IN; c++) {
                float4 w = __ldg(reinterpret_cast<const float4*>(W1) + c * (C_OUT / 4) + gl);
                acc.x = fmaf(xv[c], w.x, acc.x);
                acc.y = fmaf(xv[c], w.y, acc.y);
                acc.z = fmaf(xv[c], w.z, acc.z);
                acc.w = fmaf(xv[c], w.w, acc.w);
            }
            reinterpret_cast<float4*>(outbuf)[(long)n * (C_OUT / 4) + gl] = acc;
        } else {
#pragma unroll
            for (int k = gl * 4; k < C_OUT && k < gl * 4 + 4; k++) {
                float o = __ldg(b1 + k);
#pragma unroll
                for (int c = 0; c < C_IN; c++)
                    o = fmaf(xv[c], __ldg(W1 + c * C_OUT + k), o);
                outbuf[(long)n * C_OUT + k] = o;
            }
        }
    }
}

// ---------------- d-layer edge kernel (C_IN = 1) ------------------------------
__global__ void __launch_bounds__(256)
edge_d_kernel(int E, const float* __restrict__ xr,
              const float* __restrict__ Wm1, const float* __restrict__ bm1,
              const float* __restrict__ Wm2, const float* __restrict__ bm2,
              const float* __restrict__ W2, const float* __restrict__ b2,
              float* __restrict__ out) {
    __shared__ float4 sA[50], sB[50], sbm[50], sw[50];
    __shared__ float sW2v[20], sb2v[20];
    __shared__ float sbm2;
    int tid = threadIdx.x;
    if (tid < 50) {
        sA[tid]  = __ldg(reinterpret_cast<const float4*>(Wm1) + tid);
        sB[tid]  = __ldg(reinterpret_cast<const float4*>(Wm1 + CMSG) + tid);
        sbm[tid] = __ldg(reinterpret_cast<const float4*>(bm1) + tid);
        sw[tid]  = __ldg(reinterpret_cast<const float4*>(Wm2) + tid);
    }
    if (tid < 20) { sW2v[tid] = W2[tid]; sb2v[tid] = b2[tid]; }
    if (tid == 0) sbm2 = bm2[0];
    __syncthreads();

    int e = blockIdx.x * blockDim.x + tid;
    if (e >= E) return;
    int s = g_src[e], t = g_dst[e];
    float xi = __ldg(xr + t);
    float xj = __ldg(xr + s);

    float gate = sbm2;
#pragma unroll 2
    for (int k = 0; k < 50; k++) {
        float4 A = sA[k], B = sB[k], bm = sbm[k], w = sw[k];
        float h0 = fmaxf(fmaf(xi, A.x, fmaf(xj, B.x, bm.x)), 0.f);
        float h1 = fmaxf(fmaf(xi, A.y, fmaf(xj, B.y, bm.y)), 0.f);
        float h2 = fmaxf(fmaf(xi, A.z, fmaf(xj, B.z, bm.z)), 0.f);
        float h3 = fmaxf(fmaf(xi, A.w, fmaf(xj, B.w, bm.w)), 0.f);
        gate = fmaf(h0, w.x, gate);
        gate = fmaf(h1, w.y, gate);
        gate = fmaf(h2, w.z, gate);
        gate = fmaf(h3, w.w, gate);
    }

    float m = gate * (xi - xj);
    float* op = out + (long)t * 20;
#pragma unroll
    for (int co = 0; co < 20; co += 4) {
        float o0 = fmaf(m, sW2v[co],     sb2v[co]);
        float o1 = fmaf(m, sW2v[co + 1], sb2v[co + 1]);
        float o2 = fmaf(m, sW2v[co + 2], sb2v[co + 2]);
        float o3 = fmaf(m, sW2v[co + 3], sb2v[co + 3]);
        asm volatile("red.global.add.v4.f32 [%0], {%1, %2, %3, %4};"
                     :: "l"(op + co), "f"(o0), "f"(o1), "f"(o2), "f"(o3) : "memory");
    }
}

// ---------------- staged edge kernel v4: small chunks, 4 CTAs/SM --------------
// Tile = 256 edges, 10 chunks x 5 k4. One thread per edge owns all 20 channels.
// hbuf stride 7 float4 -> conflict-free LDS.128. smem 48.5 KB -> 4 CTAs/SM
// (32 warps): 4 independent barrier domains per SM hide the pass1/pass2
// serialization that capped the previous version at IPC ~0.65.
#define TE4    256
#define NCH4   10
#define CK4    5
#define HS4    7
#define OFF4_HBUF  0
#define SZ4_HBUF   (TE4 * HS4 * 16)           // 28672
#define OFF4_WM2   (OFF4_HBUF + SZ4_HBUF)     // 28672
#define SZ4_WM2    (CMSG * 20 * 4)            // 16000 (raw [k][20])
#define OFF4_W2    (OFF4_WM2 + SZ4_WM2)       // 44672
#define SZ4_W2     (20 * 20 * 4)              // 1600
#define OFF4_BM2   (OFF4_W2 + SZ4_W2)         // 46272
#define OFF4_B2    (OFF4_BM2 + 96)            // 46368
#define OFF4_SRC   (OFF4_B2 + 96)             // 46464
#define OFF4_DST   (OFF4_SRC + TE4 * 4)       // 47488
#define SMEM4_TOT  (OFF4_DST + TE4 * 4)       // 48512

template <int C_OUT>
__global__ void __launch_bounds__(256, 4)
edge_staged4_kernel(int E, int ntiles,
                    const float* __restrict__ xr,
                    const float4* __restrict__ pi4, const float4* __restrict__ pj4,
                    const float* __restrict__ Wm2, const float* __restrict__ bm2,
                    const float* __restrict__ W2, const float* __restrict__ b2,
                    float* __restrict__ out) {
    extern __shared__ char dyn[];
    float4* hbuf4 = reinterpret_cast<float4*>(dyn + OFF4_HBUF);
    float*  sWm2  = reinterpret_cast<float*>(dyn + OFF4_WM2);
    float*  sW2   = reinterpret_cast<float*>(dyn + OFF4_W2);
    float*  sbm2  = reinterpret_cast<float*>(dyn + OFF4_BM2);
    float*  sb2   = reinterpret_cast<float*>(dyn + OFF4_B2);
    int*    ssrc  = reinterpret_cast<int*>(dyn + OFF4_SRC);
    int*    sdst  = reinterpret_cast<int*>(dyn + OFF4_DST);

    int tid = threadIdx.x;
    {
        const float4* w4 = reinterpret_cast<const float4*>(Wm2);
        float4* d4 = reinterpret_cast<float4*>(sWm2);
        for (int i = tid; i < CMSG * 20 / 4; i += 256) d4[i] = __ldg(w4 + i);
        for (int i = tid; i < 20 * C_OUT; i += 256) sW2[i] = W2[i];
        if (tid < 20) sbm2[tid] = bm2[tid];
        if (tid < C_OUT) sb2[tid] = b2[tid];
    }

    for (int tile = blockIdx.x; tile < ntiles; tile += gridDim.x) {
        int e0 = tile * TE4;
        int tileE = E - e0; if (tileE > TE4) tileE = TE4;

        __syncthreads();
        for (int i = tid; i < TE4; i += 256) {
            int e = e0 + ((i < tileE) ? i : (tileE - 1));
            ssrc[i] = g_src[e];
            sdst[i] = g_dst[e];
        }
        __syncthreads();

        bool act = (tid < tileE);
        int s = ssrc[tid];
        int t = sdst[tid];

        u64 gate2[10];
#pragma unroll
        for (int p = 0; p < 10; p++) gate2[p] = pack2(sbm2[2 * p], sbm2[2 * p + 1]);

#pragma unroll 1
        for (int ch = 0; ch < NCH4; ch++) {
            // ---- pass 1: coalesced gather + relu into hbuf ----
#pragma unroll
            for (int it = 0; it < CK4; it++) {          // 5 iterations
                int slot = tid + it * 256;
                int e  = slot / CK4;
                int kl = slot - e * CK4;
                if (e < tileE) {
                    int kg = ch * CK4 + kl;
                    float4 a = __ldg(pi4 + (long)sdst[e] * 50 + kg);
                    float4 b = __ldg(pj4 + (long)ssrc[e] * 50 + kg);
                    float4 h;
                    h.x = fmaxf(a.x + b.x, 0.f);
                    h.y = fmaxf(a.y + b.y, 0.f);
                    h.z = fmaxf(a.z + b.z, 0.f);
                    h.w = fmaxf(a.w + b.w, 0.f);
                    hbuf4[e * HS4 + kl] = h;
                }
            }
            __syncthreads();
            // ---- pass 2: gate accumulation, all 20 channels, own edge ----
#pragma unroll
            for (int kl = 0; kl < CK4; kl++) {
                float4 h = hbuf4[tid * HS4 + kl];
                float hs[4] = {h.x, h.y, h.z, h.w};
                const float* wk = sWm2 + ((ch * CK4 + kl) * 4) * 20;
#pragma unroll
                for (int j = 0; j < 4; j++) {
                    const ulonglong2* wr =
                        reinterpret_cast<const ulonglong2*>(wk + j * 20);
                    u64 hb = packbb(hs[j]);
#pragma unroll
                    for (int q = 0; q < 5; q++) {
                        ulonglong2 w = wr[q];
                        fma2(gate2[2 * q],     hb, w.x);
                        fma2(gate2[2 * q + 1], hb, w.y);
                    }
                }
            }
            __syncthreads();
        }

        // ---- epilogue: msg + scatter (all in-thread) ----
        float m[20];
        {
            const float4* xt4 = reinterpret_cast<const float4*>(xr + (long)t * 20);
            const float4* xs4 = reinterpret_cast<const float4*>(xr + (long)s * 20);
#pragma unroll
            for (int q = 0; q < 5; q++) {
                float4 xt = __ldg(xt4 + q);
                float4 xs = __ldg(xs4 + q);
                float2 g0 = un2(gate2[2 * q]);
                float2 g1 = un2(gate2[2 * q + 1]);
                m[4 * q + 0] = g0.x * (xt.x - xs.x);
                m[4 * q + 1] = g0.y * (xt.y - xs.y);
                m[4 * q + 2] = g1.x * (xt.z - xs.z);
                m[4 * q + 3] = g1.y * (xt.w - xs.w);
            }
        }

        if constexpr (C_OUT == 20) {
            u64 o2[10];
#pragma unroll
            for (int p = 0; p < 10; p++) o2[p] = pack2(sb2[2 * p], sb2[2 * p + 1]);
#pragma unroll
            for (int c = 0; c < 20; c++) {
                u64 mb = packbb(m[c]);
                const ulonglong2* wr =
                    reinterpret_cast<const ulonglong2*>(sW2 + c * 20);
#pragma unroll
                for (int q = 0; q < 5; q++) {
                    ulonglong2 w = wr[q];
                    fma2(o2[2 * q],     mb, w.x);
                    fma2(o2[2 * q + 1], mb, w.y);
                }
            }
            if (act) {
                float* op = out + (long)t * 20;
#pragma unroll
                for (int q = 0; q < 5; q++) {
                    float2 a = un2(o2[2 * q]);
                    float2 b = un2(o2[2 * q + 1]);
                    asm volatile("red.global.add.v4.f32 [%0], {%1, %2, %3, %4};"
                                 :: "l"(op + 4 * q), "f"(a.x), "f"(a.y), "f"(b.x), "f"(b.y)
                                 : "memory");
                }
            }
        } else {
            float o = sb2[0];
#pragma unroll
            for (int c = 0; c < 20; c++) o = fmaf(m[c], sW2[c], o);
            if (act)
                asm volatile("red.global.add.f32 [%0], %1;" :: "l"(out + t), "f"(o) : "memory");
        }
    }
}

// ---------------- launcher ----------------------------------------------------
extern "C" void kernel_launch(void* const* d_in, const int* in_sizes, int n_in,
                              void* d_out, int out_size) {
    const float* feat  = (const float*)d_in[0];
    const void*  edges = d_in[1];
    int E = in_sizes[1] / 2;
    if (E > EMAX) E = EMAX;

    const float* prm[27];
    for (int i = 0; i < 27; i++) prm[i] = (const float*)d_in[i];
    // per-layer param base: d=3, h=11, o=19; order W1,b1,Wm1,bm1,Wm2,bm2,W2,b2

    float *xr, *pi, *pj, *bufA, *bufB;
    cudaGetSymbolAddress((void**)&xr, g_xr);
    cudaGetSymbolAddress((void**)&pi, g_pi);
    cudaGetSymbolAddress((void**)&pj, g_pj);
    cudaGetSymbolAddress((void**)&bufA, g_bufA);
    cudaGetSymbolAddress((void**)&bufB, g_bufB);
    float4* pi4 = (float4*)pi;
    float4* pj4 = (float4*)pj;
    float* outf = (float*)d_out;

    cudaFuncSetAttribute(edge_staged4_kernel<20>,
                         cudaFuncAttributeMaxDynamicSharedMemorySize, SMEM4_TOT);
    cudaFuncSetAttribute(edge_staged4_kernel<1>,
                         cudaFuncAttributeMaxDynamicSharedMemorySize, SMEM4_TOT);

    const int TB = 256;
    int gn20 = (NNODES * 55 + TB - 1) / TB;
    int gn1  = (NNODES * 51 + TB - 1) / TB;
    int gnd  = (NNODES + TB - 1) / TB;
    int ge   = (E + TB - 1) / TB;
    int ntiles = (E + TE4 - 1) / TE4;
    int gst = 4 * 148; if (gst > ntiles) gst = ntiles;

    convert_kernel<<<ge, TB>>>(edges, E);

    // layer d: 1 -> 20
    node_d_kernel<<<gnd, TB>>>(feat, prm[3], prm[4], xr, bufA);
    edge_d_kernel<<<ge, TB>>>(E, xr, prm[5], prm[6], prm[7], prm[8], prm[9], prm[10], bufA);

    // 3x layer h: 20 -> 20
    node_kernel<20><<<gn20, TB>>>(bufA, prm[11], prm[12], prm[13], prm[14],
                                  xr, pi4, pj4, bufB);
    edge_staged4_kernel<20><<<gst, TB, SMEM4_TOT>>>(E, ntiles, xr, pi4, pj4,
                                                    prm[15], prm[16], prm[17], prm[18], bufB);

    node_kernel<20><<<gn20, TB>>>(bufB, prm[11], prm[12], prm[13], prm[14],
                                  xr, pi4, pj4, bufA);
    edge_staged4_kernel<20><<<gst, TB, SMEM4_TOT>>>(E, ntiles, xr, pi4, pj4,
                                                    prm[15], prm[16], prm[17], prm[18], bufA);

    node_kernel<20><<<gn20, TB>>>(bufA, prm[11], prm[12], prm[13], prm[14],
                                  xr, pi4, pj4, bufB);
    edge_staged4_kernel<20><<<gst, TB, SMEM4_TOT>>>(E, ntiles, xr, pi4, pj4,
                                                    prm[15], prm[16], prm[17], prm[18], bufB);

    // layer o: 20 -> 1
    node_kernel<1><<<gn1, TB>>>(bufB, prm[19], prm[20], prm[21], prm[22],
                                xr, pi4, pj4, outf);
    edge_staged4_kernel<1><<<gst, TB, SMEM4_TOT>>>(E, ntiles, xr, pi4, pj4,
                                                   prm[23], prm[24], prm[25], prm[26], outf);
}

// round 17
// speedup vs baseline: 1.1691x; 1.1691x over previous
#include <cuda_runtime.h>

typedef unsigned long long u64;

#define NNODES 25000
#define CMSG   200
#define EMAX   400000

// ---------------- scratch (no allocation allowed -> device globals) ----------
static __device__ float g_xr[NNODES * 20];
static __device__ float g_pi[NNODES * CMSG];
static __device__ float g_pj[NNODES * CMSG];
static __device__ float g_bufA[NNODES * 20];
static __device__ float g_bufB[NNODES * 20];
static __device__ int   g_src[EMAX];
static __device__ int   g_dst[EMAX];

// ---------------- packed fp32x2 helpers --------------------------------------
__device__ __forceinline__ u64 pack2(float lo, float hi) {
    u64 r; asm("mov.b64 %0, {%1, %2};" : "=l"(r) : "f"(lo), "f"(hi)); return r;
}
__device__ __forceinline__ u64 packbb(float v) { return pack2(v, v); }
__device__ __forceinline__ void fma2(u64& d, u64 a, u64 b) {
    asm("fma.rn.f32x2 %0, %1, %2, %0;" : "+l"(d) : "l"(a), "l"(b));
}
__device__ __forceinline__ float2 un2(u64 v) {
    float2 f; asm("mov.b64 {%0, %1}, %2;" : "=f"(f.x), "=f"(f.y) : "l"(v)); return f;
}

// ---------------- edge conversion with inline per-block detect ----------------
__global__ void convert_kernel(const void* __restrict__ edges_raw, int E) {
    __shared__ int s_is64;
    int tid = threadIdx.x;
    if (tid < 32) {
        int idx = 2 * tid + 1;                  // high words of first 32 int64
        int v = (idx < 2 * E) ? ((const int*)edges_raw)[idx] : 0;
        unsigned nz = __ballot_sync(0xFFFFFFFFu, v != 0);
        if (tid == 0) s_is64 = (nz == 0) ? 1 : 0;
    }
    __syncthreads();
    int e = blockIdx.x * blockDim.x + tid;
    if (e >= E) return;
    if (s_is64) {
        const long long* p = (const long long*)edges_raw;
        g_src[e] = (int)p[e];
        g_dst[e] = (int)p[E + e];
    } else {
        const int* p = (const int*)edges_raw;
        g_src[e] = p[e];
        g_dst[e] = p[E + e];
    }
}

// ---------------- d-layer node kernel ----------------------------------------
__global__ void node_d_kernel(const float* __restrict__ feat,
                              const float* __restrict__ W1, const float* __restrict__ b1,
                              float* __restrict__ xr, float* __restrict__ out) {
    int n = blockIdx.x * blockDim.x + threadIdx.x;
    if (n >= NNODES) return;
    float x = __ldg(feat + n);
    xr[n] = x;
    float4* o4 = reinterpret_cast<float4*>(out + n * 20);
    const float4* w4 = reinterpret_cast<const float4*>(W1);
    const float4* b4 = reinterpret_cast<const float4*>(b1);
#pragma unroll
    for (int g = 0; g < 5; g++) {
        float4 w = __ldg(w4 + g);
        float4 b = __ldg(b4 + g);
        o4[g] = make_float4(fmaf(x, w.x, b.x), fmaf(x, w.y, b.y),
                            fmaf(x, w.z, b.z), fmaf(x, w.w, b.w));
    }
}

// ---------------- node precompute: 2 nodes per thread -------------------------
// Thread (pair, g) loads each weight float4 ONCE and applies it to both nodes
// of the pair -> halves the L1 weight-reload traffic that bound this kernel
// (43us measured ~= the 800MB/L1-BW floor; now ~half).
template <int C_OUT>
__global__ void node2_kernel(const float* __restrict__ xin,
                             const float* __restrict__ W1, const float* __restrict__ b1,
                             const float* __restrict__ Wm1, const float* __restrict__ bm1,
                             float* __restrict__ xr,
                             float4* __restrict__ pi4, float4* __restrict__ pj4,
                             float* __restrict__ outbuf) {
    constexpr int C_IN = 20;
    constexpr int K4   = CMSG / 4;            // 50
    constexpr int GL   = (C_OUT + 3) / 4;
    constexpr int TOTG = K4 + GL;             // 55 or 51
    constexpr int NPAIR = NNODES / 2;         // 12500
    int idx = blockIdx.x * blockDim.x + threadIdx.x;
    if (idx >= NPAIR * TOTG) return;
    int pair = idx / TOTG;
    int g = idx - pair * TOTG;
    int n0 = 2 * pair, n1 = n0 + 1;

    float xv0[C_IN], xv1[C_IN];
    {
        const float4* x0 = reinterpret_cast<const float4*>(xin + (long)n0 * C_IN);
        const float4* x1 = reinterpret_cast<const float4*>(xin + (long)n1 * C_IN);
#pragma unroll
        for (int q = 0; q < C_IN / 4; q++) {
            float4 v0 = __ldg(x0 + q);
            float4 v1 = __ldg(x1 + q);
            xv0[4 * q + 0] = fmaxf(v0.x, 0.f); xv1[4 * q + 0] = fmaxf(v1.x, 0.f);
            xv0[4 * q + 1] = fmaxf(v0.y, 0.f); xv1[4 * q + 1] = fmaxf(v1.y, 0.f);
            xv0[4 * q + 2] = fmaxf(v0.z, 0.f); xv1[4 * q + 2] = fmaxf(v1.z, 0.f);
            xv0[4 * q + 3] = fmaxf(v0.w, 0.f); xv1[4 * q + 3] = fmaxf(v1.w, 0.f);
        }
    }
    if (g == 0) {
        float4* r0 = reinterpret_cast<float4*>(xr + (long)n0 * C_IN);
        float4* r1 = reinterpret_cast<float4*>(xr + (long)n1 * C_IN);
#pragma unroll
        for (int q = 0; q < C_IN / 4; q++) {
            r0[q] = make_float4(xv0[4 * q], xv0[4 * q + 1], xv0[4 * q + 2], xv0[4 * q + 3]);
            r1[q] = make_float4(xv1[4 * q], xv1[4 * q + 1], xv1[4 * q + 2], xv1[4 * q + 3]);
        }
    }

    if (g < K4) {
        const float4* W4 = reinterpret_cast<const float4*>(Wm1);  // [2*C_IN][K4]
        float4 bm = __ldg(reinterpret_cast<const float4*>(bm1) + g);
        float4 ai0 = bm, ai1 = bm;
        float4 aj0 = make_float4(0.f, 0.f, 0.f, 0.f);
        float4 aj1 = make_float4(0.f, 0.f, 0.f, 0.f);
#pragma unroll
        for (int c = 0; c < C_IN; c++) {
            float4 wi = __ldg(W4 + c * K4 + g);
            float x0 = xv0[c], x1 = xv1[c];
            ai0.x = fmaf(x0, wi.x, ai0.x); ai1.x = fmaf(x1, wi.x, ai1.x);
            ai0.y = fmaf(x0, wi.y, ai0.y); ai1.y = fmaf(x1, wi.y, ai1.y);
            ai0.z = fmaf(x0, wi.z, ai0.z); ai1.z = fmaf(x1, wi.z, ai1.z);
            ai0.w = fmaf(x0, wi.w, ai0.w); ai1.w = fmaf(x1, wi.w, ai1.w);
            float4 wj = __ldg(W4 + (C_IN + c) * K4 + g);
            aj0.x = fmaf(x0, wj.x, aj0.x); aj1.x = fmaf(x1, wj.x, aj1.x);
            aj0.y = fmaf(x0, wj.y, aj0.y); aj1.y = fmaf(x1, wj.y, aj1.y);
            aj0.z = fmaf(x0, wj.z, aj0.z); aj1.z = fmaf(x1, wj.z, aj1.z);
            aj0.w = fmaf(x0, wj.w, aj0.w); aj1.w = fmaf(x1, wj.w, aj1.w);
        }
        pi4[(long)n0 * K4 + g] = ai0;
        pj4[(long)n0 * K4 + g] = aj0;
        pi4[(long)n1 * K4 + g] = ai1;
        pj4[(long)n1 * K4 + g] = aj1;
    } else {
        int gl = g - K4;
        if constexpr (C_OUT % 4 == 0) {
            float4 bb = __ldg(reinterpret_cast<const float4*>(b1) + gl);
            float4 a0 = bb, a1 = bb;
#pragma unroll
            for (int c = 0; c < C_IN; c++) {
                float4 w = __ldg(reinterpret_cast<const float4*>(W1) + c * (C_OUT / 4) + gl);
                float x0 = xv0[c], x1 = xv1[c];
                a0.x = fmaf(x0, w.x, a0.x); a1.x = fmaf(x1, w.x, a1.x);
                a0.y = fmaf(x0, w.y, a0.y); a1.y = fmaf(x1, w.y, a1.y);
                a0.z = fmaf(x0, w.z, a0.z); a1.z = fmaf(x1, w.z, a1.z);
                a0.w = fmaf(x0, w.w, a0.w); a1.w = fmaf(x1, w.w, a1.w);
            }
            reinterpret_cast<float4*>(outbuf)[(long)n0 * (C_OUT / 4) + gl] = a0;
            reinterpret_cast<float4*>(outbuf)[(long)n1 * (C_OUT / 4) + gl] = a1;
        } else {
#pragma unroll
            for (int k = gl * 4; k < C_OUT && k < gl * 4 + 4; k++) {
                float o0 = __ldg(b1 + k), o1 = o0;
#pragma unroll
                for (int c = 0; c < C_IN; c++) {
                    float w = __ldg(W1 + c * C_OUT + k);
                    o0 = fmaf(xv0[c], w, o0);
                    o1 = fmaf(xv1[c], w, o1);
                }
                outbuf[(long)n0 * C_OUT + k] = o0;
                outbuf[(long)n1 * C_OUT + k] = o1;
            }
        }
    }
}

// ---------------- d-layer edge kernel (C_IN = 1) ------------------------------
__global__ void __launch_bounds__(256)
edge_d_kernel(int E, const float* __restrict__ xr,
              const float* __restrict__ Wm1, const float* __restrict__ bm1,
              const float* __restrict__ Wm2, const float* __restrict__ bm2,
              const float* __restrict__ W2, const float* __restrict__ b2,
              float* __restrict__ out) {
    __shared__ float4 sA[50], sB[50], sbm[50], sw[50];
    __shared__ float sW2v[20], sb2v[20];
    __shared__ float sbm2;
    int tid = threadIdx.x;
    if (tid < 50) {
        sA[tid]  = __ldg(reinterpret_cast<const float4*>(Wm1) + tid);
        sB[tid]  = __ldg(reinterpret_cast<const float4*>(Wm1 + CMSG) + tid);
        sbm[tid] = __ldg(reinterpret_cast<const float4*>(bm1) + tid);
        sw[tid]  = __ldg(reinterpret_cast<const float4*>(Wm2) + tid);
    }
    if (tid < 20) { sW2v[tid] = W2[tid]; sb2v[tid] = b2[tid]; }
    if (tid == 0) sbm2 = bm2[0];
    __syncthreads();

    int e = blockIdx.x * blockDim.x + tid;
    if (e >= E) return;
    int s = g_src[e], t = g_dst[e];
    float xi = __ldg(xr + t);
    float xj = __ldg(xr + s);

    float gate = sbm2;
#pragma unroll 2
    for (int k = 0; k < 50; k++) {
        float4 A = sA[k], B = sB[k], bm = sbm[k], w = sw[k];
        float h0 = fmaxf(fmaf(xi, A.x, fmaf(xj, B.x, bm.x)), 0.f);
        float h1 = fmaxf(fmaf(xi, A.y, fmaf(xj, B.y, bm.y)), 0.f);
        float h2 = fmaxf(fmaf(xi, A.z, fmaf(xj, B.z, bm.z)), 0.f);
        float h3 = fmaxf(fmaf(xi, A.w, fmaf(xj, B.w, bm.w)), 0.f);
        gate = fmaf(h0, w.x, gate);
        gate = fmaf(h1, w.y, gate);
        gate = fmaf(h2, w.z, gate);
        gate = fmaf(h3, w.w, gate);
    }

    float m = gate * (xi - xj);
    float* op = out + (long)t * 20;
#pragma unroll
    for (int co = 0; co < 20; co += 4) {
        float o0 = fmaf(m, sW2v[co],     sb2v[co]);
        float o1 = fmaf(m, sW2v[co + 1], sb2v[co + 1]);
        float o2 = fmaf(m, sW2v[co + 2], sb2v[co + 2]);
        float o3 = fmaf(m, sW2v[co + 3], sb2v[co + 3]);
        asm volatile("red.global.add.v4.f32 [%0], {%1, %2, %3, %4};"
                     :: "l"(op + co), "f"(o0), "f"(o1), "f"(o2), "f"(o3) : "memory");
    }
}

// ---------------- staged edge kernel (R13 shape: proven best) -----------------
#define TE3    256
#define NCH3   5
#define CK43   10
#define HS3    11
#define OFF3_HBUF  0
#define SZ3_HBUF   (TE3 * HS3 * 16)           // 45056
#define OFF3_WM2   (OFF3_HBUF + SZ3_HBUF)     // 45056
#define SZ3_WM2    (CMSG * 20 * 4)            // 16000 (raw [k][20])
#define OFF3_W2    (OFF3_WM2 + SZ3_WM2)       // 61056
#define SZ3_W2     (20 * 20 * 4)              // 1600
#define OFF3_BM2   (OFF3_W2 + SZ3_W2)         // 62656
#define OFF3_B2    (OFF3_BM2 + 96)            // 62752
#define OFF3_SRC   (OFF3_B2 + 96)             // 62848
#define OFF3_DST   (OFF3_SRC + TE3 * 4)       // 63872
#define SMEM3_TOT  (OFF3_DST + TE3 * 4)       // 64896

template <int C_OUT>
__global__ void __launch_bounds__(256, 3)
edge_staged3_kernel(int E, int ntiles,
                    const float* __restrict__ xr,
                    const float4* __restrict__ pi4, const float4* __restrict__ pj4,
                    const float* __restrict__ Wm2, const float* __restrict__ bm2,
                    const float* __restrict__ W2, const float* __restrict__ b2,
                    float* __restrict__ out) {
    extern __shared__ char dyn[];
    float4* hbuf4 = reinterpret_cast<float4*>(dyn + OFF3_HBUF);
    float*  sWm2  = reinterpret_cast<float*>(dyn + OFF3_WM2);
    float*  sW2   = reinterpret_cast<float*>(dyn + OFF3_W2);
    float*  sbm2  = reinterpret_cast<float*>(dyn + OFF3_BM2);
    float*  sb2   = reinterpret_cast<float*>(dyn + OFF3_B2);
    int*    ssrc  = reinterpret_cast<int*>(dyn + OFF3_SRC);
    int*    sdst  = reinterpret_cast<int*>(dyn + OFF3_DST);

    int tid = threadIdx.x;
    {
        const float4* w4 = reinterpret_cast<const float4*>(Wm2);
        float4* d4 = reinterpret_cast<float4*>(sWm2);
        for (int i = tid; i < CMSG * 20 / 4; i += 256) d4[i] = __ldg(w4 + i);
        for (int i = tid; i < 20 * C_OUT; i += 256) sW2[i] = W2[i];
        if (tid < 20) sbm2[tid] = bm2[tid];
        if (tid < C_OUT) sb2[tid] = b2[tid];
    }

    for (int tile = blockIdx.x; tile < ntiles; tile += gridDim.x) {
        int e0 = tile * TE3;
        int tileE = E - e0; if (tileE > TE3) tileE = TE3;

        __syncthreads();
        for (int i = tid; i < TE3; i += 256) {
            int e = e0 + ((i < tileE) ? i : (tileE - 1));
            ssrc[i] = g_src[e];
            sdst[i] = g_dst[e];
        }
        __syncthreads();

        bool act = (tid < tileE);
        int s = ssrc[tid];
        int t = sdst[tid];

        u64 gate2[10];
#pragma unroll
        for (int p = 0; p < 10; p++) gate2[p] = pack2(sbm2[2 * p], sbm2[2 * p + 1]);

#pragma unroll 1
        for (int ch = 0; ch < NCH3; ch++) {
            // ---- pass 1: coalesced gather + relu into hbuf ----
#pragma unroll
            for (int it = 0; it < (TE3 * CK43) / 256; it++) {
                int slot = tid + it * 256;
                int e  = slot / CK43;
                int kl = slot - e * CK43;
                if (e < tileE) {
                    int kg = ch * CK43 + kl;
                    float4 a = __ldg(pi4 + (long)sdst[e] * 50 + kg);
                    float4 b = __ldg(pj4 + (long)ssrc[e] * 50 + kg);
                    float4 h;
                    h.x = fmaxf(a.x + b.x, 0.f);
                    h.y = fmaxf(a.y + b.y, 0.f);
                    h.z = fmaxf(a.z + b.z, 0.f);
                    h.w = fmaxf(a.w + b.w, 0.f);
                    hbuf4[e * HS3 + kl] = h;
                }
            }
            __syncthreads();
            // ---- pass 2: gate accumulation, all 20 channels, own edge ----
#pragma unroll 2
            for (int kl = 0; kl < CK43; kl++) {
                float4 h = hbuf4[tid * HS3 + kl];
                float hs[4] = {h.x, h.y, h.z, h.w};
                const float* wk = sWm2 + ((ch * CK43 + kl) * 4) * 20;
#pragma unroll
                for (int j = 0; j < 4; j++) {
                    const ulonglong2* wr =
                        reinterpret_cast<const ulonglong2*>(wk + j * 20);
                    u64 hb = packbb(hs[j]);
#pragma unroll
                    for (int q = 0; q < 5; q++) {
                        ulonglong2 w = wr[q];
                        fma2(gate2[2 * q],     hb, w.x);
                        fma2(gate2[2 * q + 1], hb, w.y);
                    }
                }
            }
            __syncthreads();
        }

        // ---- epilogue: msg + scatter (all in-thread) ----
        float m[20];
        {
            const float4* xt4 = reinterpret_cast<const float4*>(xr + (long)t * 20);
            const float4* xs4 = reinterpret_cast<const float4*>(xr + (long)s * 20);
#pragma unroll
            for (int q = 0; q < 5; q++) {
                float4 xt = __ldg(xt4 + q);
                float4 xs = __ldg(xs4 + q);
                float2 g0 = un2(gate2[2 * q]);
                float2 g1 = un2(gate2[2 * q + 1]);
                m[4 * q + 0] = g0.x * (xt.x - xs.x);
                m[4 * q + 1] = g0.y * (xt.y - xs.y);
                m[4 * q + 2] = g1.x * (xt.z - xs.z);
                m[4 * q + 3] = g1.y * (xt.w - xs.w);
            }
        }

        if constexpr (C_OUT == 20) {
            u64 o2[10];
#pragma unroll
            for (int p = 0; p < 10; p++) o2[p] = pack2(sb2[2 * p], sb2[2 * p + 1]);
#pragma unroll
            for (int c = 0; c < 20; c++) {
                u64 mb = packbb(m[c]);
                const ulonglong2* wr =
                    reinterpret_cast<const ulonglong2*>(sW2 + c * 20);
#pragma unroll
                for (int q = 0; q < 5; q++) {
                    ulonglong2 w = wr[q];
                    fma2(o2[2 * q],     mb, w.x);
                    fma2(o2[2 * q + 1], mb, w.y);
                }
            }
            if (act) {
                float* op = out + (long)t * 20;
#pragma unroll
                for (int q = 0; q < 5; q++) {
                    float2 a = un2(o2[2 * q]);
                    float2 b = un2(o2[2 * q + 1]);
                    asm volatile("red.global.add.v4.f32 [%0], {%1, %2, %3, %4};"
                                 :: "l"(op + 4 * q), "f"(a.x), "f"(a.y), "f"(b.x), "f"(b.y)
                                 : "memory");
                }
            }
        } else {
            float o = sb2[0];
#pragma unroll
            for (int c = 0; c < 20; c++) o = fmaf(m[c], sW2[c], o);
            if (act)
                asm volatile("red.global.add.f32 [%0], %1;" :: "l"(out + t), "f"(o) : "memory");
        }
    }
}

// ---------------- launcher ----------------------------------------------------
extern "C" void kernel_launch(void* const* d_in, const int* in_sizes, int n_in,
                              void* d_out, int out_size) {
    const float* feat  = (const float*)d_in[0];
    const void*  edges = d_in[1];
    int E = in_sizes[1] / 2;
    if (E > EMAX) E = EMAX;

    const float* prm[27];
    for (int i = 0; i < 27; i++) prm[i] = (const float*)d_in[i];
    // per-layer param base: d=3, h=11, o=19; order W1,b1,Wm1,bm1,Wm2,bm2,W2,b2

    float *xr, *pi, *pj, *bufA, *bufB;
    cudaGetSymbolAddress((void**)&xr, g_xr);
    cudaGetSymbolAddress((void**)&pi, g_pi);
    cudaGetSymbolAddress((void**)&pj, g_pj);
    cudaGetSymbolAddress((void**)&bufA, g_bufA);
    cudaGetSymbolAddress((void**)&bufB, g_bufB);
    float4* pi4 = (float4*)pi;
    float4* pj4 = (float4*)pj;
    float* outf = (float*)d_out;

    cudaFuncSetAttribute(edge_staged3_kernel<20>,
                         cudaFuncAttributeMaxDynamicSharedMemorySize, SMEM3_TOT);
    cudaFuncSetAttribute(edge_staged3_kernel<1>,
                         cudaFuncAttributeMaxDynamicSharedMemorySize, SMEM3_TOT);

    const int TB = 256;
    int gn20 = (NNODES / 2 * 55 + TB - 1) / TB;   // node2: C_OUT = 20 (TOTG=55)
    int gn1  = (NNODES / 2 * 51 + TB - 1) / TB;   // node2: C_OUT = 1  (TOTG=51)
    int gnd  = (NNODES + TB - 1) / TB;
    int ge   = (E + TB - 1) / TB;
    int ntiles = (E + TE3 - 1) / TE3;
    int gst = 3 * 148; if (gst > ntiles) gst = ntiles;

    convert_kernel<<<ge, TB>>>(edges, E);

    // layer d: 1 -> 20
    node_d_kernel<<<gnd, TB>>>(feat, prm[3], prm[4], xr, bufA);
    edge_d_kernel<<<ge, TB>>>(E, xr, prm[5], prm[6], prm[7], prm[8], prm[9], prm[10], bufA);

    // 3x layer h: 20 -> 20
    node2_kernel<20><<<gn20, TB>>>(bufA, prm[11], prm[12], prm[13], prm[14],
                                   xr, pi4, pj4, bufB);
    edge_staged3_kernel<20><<<gst, TB, SMEM3_TOT>>>(E, ntiles, xr, pi4, pj4,
                                                    prm[15], prm[16], prm[17], prm[18], bufB);

    node2_kernel<20><<<gn20, TB>>>(bufB, prm[11], prm[12], prm[13], prm[14],
                                   xr, pi4, pj4, bufA);
    edge_staged3_kernel<20><<<gst, TB, SMEM3_TOT>>>(E, ntiles, xr, pi4, pj4,
                                                    prm[15], prm[16], prm[17], prm[18], bufA);

    node2_kernel<20><<<gn20, TB>>>(bufA, prm[11], prm[12], prm[13], prm[14],
                                   xr, pi4, pj4, bufB);
    edge_staged3_kernel<20><<<gst, TB, SMEM3_TOT>>>(E, ntiles, xr, pi4, pj4,
                                                    prm[15], prm[16], prm[17], prm[18], bufB);

    // layer o: 20 -> 1
    node2_kernel<1><<<gn1, TB>>>(bufB, prm[19], prm[20], prm[21], prm[22],
                                 xr, pi4, pj4, outf);
    edge_staged3_kernel<1><<<gst, TB, SMEM3_TOT>>>(E, ntiles, xr, pi4, pj4,
                                                   prm[23], prm[24], prm[25], prm[26], outf);
}